// round 7
// baseline (speedup 1.0000x reference)
#include <cuda_runtime.h>
#include <cuda_bf16.h>
#include <stdint.h>

#define THREADS 256
#define ITEMS   8
#define CHUNK   (THREADS * ITEMS)   // 2048
#define NWARPS  (THREADS / 32)      // 8

__global__ __launch_bounds__(THREADS, 2)
void traj_scan_kernel(const int*   __restrict__ states,
                      const float* __restrict__ e0s,
                      const float* __restrict__ speed0,
                      const float* __restrict__ speed1,
                      const float* __restrict__ x0,
                      float*       __restrict__ X,
                      int T, int P)
{
    extern __shared__ char dyn[];
    uint16_t* sm_pk = (uint16_t*)dyn;                    // [P*256] packed tb|s0
    int*      sm_ex = (int*)(dyn + (size_t)P * THREADS * 2); // [P*8] excl tumbles
    __shared__ float s_fx[2][NWARPS], s_fy[2][NWARPS], s_fz[2][NWARPS];

    const int b = blockIdx.x;
    const int*   srow = states + (size_t)b * T;
    const float* erow = e0s    + (size_t)b * (T + 1) * 3;
    float*       xrow = X      + (size_t)b * T * 3;

    const float sp0 = speed0[b];
    const float sp1 = speed1[b];
    const float DT  = 0.1f;

    const int tid  = threadIdx.x;
    const int lane = tid & 31;
    const int wid  = tid >> 5;

    // ================= PHASE 1: pack states + global tumble prefix ========
    for (int c = 0; c < P; c++) {
        const int t0 = c * CHUNK + tid * ITEMS;
        int s[8] = {0,0,0,0,0,0,0,0};
        if (t0 + ITEMS <= T) {
            int4 a = *reinterpret_cast<const int4*>(srow + t0);
            int4 bb = *reinterpret_cast<const int4*>(srow + t0 + 4);
            s[0]=a.x; s[1]=a.y; s[2]=a.z; s[3]=a.w;
            s[4]=bb.x; s[5]=bb.y; s[6]=bb.z; s[7]=bb.w;
        } else {
            #pragma unroll
            for (int i = 0; i < ITEMS; i++)
                if (t0 + i < T) s[i] = srow[t0 + i];
        }
        unsigned tb = 0, s0 = 0;
        #pragma unroll
        for (int i = 0; i < ITEMS; i++) {
            tb |= (unsigned)(s[i] == 2) << i;
            s0 |= (unsigned)(s[i] == 0) << i;
        }
        sm_pk[c * THREADS + tid] = (uint16_t)(tb | (s0 << 8));
        const int wt = __reduce_add_sync(0xffffffffu, __popc(tb));
        if (lane == 0) sm_ex[c * NWARPS + wid] = wt;
    }
    __syncthreads();
    if (wid == 0) {
        const int ntot = P * NWARPS;
        int carry = 0;
        for (int basej = 0; basej < ntot; basej += 32) {
            const int j = basej + lane;
            const int v = (j < ntot) ? sm_ex[j] : 0;
            int sc = v;
            #pragma unroll
            for (int d = 1; d < 32; d <<= 1) {
                int y = __shfl_up_sync(0xffffffffu, sc, d);
                if (lane >= d) sc += y;
            }
            const int tot = __shfl_sync(0xffffffffu, sc, 31);
            if (j < ntot) sm_ex[j] = carry + sc - v;   // exclusive
            carry += tot;
        }
    }
    __syncthreads();

    // issue the 24 gathers for chunk c given its packed word
    #define ISSUE_FOR_CHUNK(c, pk, g)                                         \
        do {                                                                  \
            const unsigned _tb = (pk) & 0xffu;                                \
            const int _cnt = __popc(_tb);                                     \
            int _sc = _cnt;                                                   \
            _Pragma("unroll")                                                 \
            for (int _d = 1; _d < 32; _d <<= 1) {                             \
                int _y = __shfl_up_sync(0xffffffffu, _sc, _d);                \
                if (lane >= _d) _sc += _y;                                    \
            }                                                                 \
            const int _kb = sm_ex[(c) * NWARPS + wid] + (_sc - _cnt);         \
            _Pragma("unroll")                                                 \
            for (int _i = 0; _i < ITEMS; _i++) {                              \
                const int _k = _kb + __popc(_tb & ((2u << _i) - 1u));         \
                const float* _e = erow + (size_t)_k * 3;                      \
                g[3 * _i + 0] = __ldg(_e + 0);                                \
                g[3 * _i + 1] = __ldg(_e + 1);                                \
                g[3 * _i + 2] = __ldg(_e + 2);                                \
            }                                                                 \
        } while (0)

    // ================= PHASE 2: serial float scan over chunks ==============
    float g[24];
    uint16_t pk_cur = sm_pk[tid];
    ISSUE_FOR_CHUNK(0, pk_cur, g);

    const float ox = x0[3 * b + 0];
    const float oy = x0[3 * b + 1];
    const float oz = x0[3 * b + 2];
    float carry_x = 0.f, carry_y = 0.f, carry_z = 0.f;
    int parity = 0;

    for (int i = 0; i < P; i++, parity ^= 1) {
        const bool hn = (i + 1) < P;
        const uint16_t pk_next = hn ? sm_pk[(i + 1) * THREADS + tid] : (uint16_t)0;

        // ---- consume gathers for chunk i -> local inclusive float3 prefix
        const int t0 = i * CHUNK + tid * ITEMS;
        const unsigned tb  = pk_cur & 0xffu;
        const unsigned s0m = pk_cur >> 8;
        float vx[ITEMS], vy[ITEMS], vz[ITEMS];
        float ax = 0.f, ay = 0.f, az = 0.f;
        #pragma unroll
        for (int j = 0; j < ITEMS; j++) {
            const bool zero = ((tb >> j) & 1u) || (t0 + j >= T);
            const float sp = zero ? 0.f : (((s0m >> j) & 1u) ? sp0 : sp1);
            ax = fmaf(g[3 * j + 0], sp, ax);
            ay = fmaf(g[3 * j + 1], sp, ay);
            az = fmaf(g[3 * j + 2], sp, az);
            vx[j] = ax; vy[j] = ay; vz[j] = az;
        }

        // ---- issue gathers for chunk i+1 (k fully precomputed) ----
        if (hn) ISSUE_FOR_CHUNK(i + 1, pk_next, g);

        // ---- float-only block scan, ONE barrier ----
        float sx = ax, sy = ay, sz = az;
        #pragma unroll
        for (int d = 1; d < 32; d <<= 1) {
            const float tx = __shfl_up_sync(0xffffffffu, sx, d);
            const float ty = __shfl_up_sync(0xffffffffu, sy, d);
            const float tz = __shfl_up_sync(0xffffffffu, sz, d);
            if (lane >= d) { sx += tx; sy += ty; sz += tz; }
        }
        if (lane == 31) {
            s_fx[parity][wid] = sx; s_fy[parity][wid] = sy; s_fz[parity][wid] = sz;
        }
        __syncthreads();
        float wxe = 0.f, wye = 0.f, wze = 0.f;
        float txs = 0.f, tys = 0.f, tzs = 0.f;
        #pragma unroll
        for (int j = 0; j < NWARPS; j++) {
            const float fx = s_fx[parity][j];
            const float fy = s_fy[parity][j];
            const float fz = s_fz[parity][j];
            if (j < wid) { wxe += fx; wye += fy; wze += fz; }
            txs += fx; tys += fy; tzs += fz;
        }
        const float bxc = fmaf(DT, carry_x + wxe + (sx - ax), ox);
        const float byc = fmaf(DT, carry_y + wye + (sy - ay), oy);
        const float bzc = fmaf(DT, carry_z + wze + (sz - az), oz);
        carry_x += txs; carry_y += tys; carry_z += tzs;

        // ---- stores for chunk i (streaming, 6x float4) ----
        if (t0 + ITEMS <= T) {
            float4* q = reinterpret_cast<float4*>(xrow + (size_t)t0 * 3);
            #pragma unroll
            for (int gg = 0; gg < 6; gg++) {
                float o[4];
                #pragma unroll
                for (int j4 = 0; j4 < 4; j4++) {
                    const int f = gg * 4 + j4;
                    const int it = f / 3;
                    const int d  = f % 3;
                    const float bc = (d == 0) ? bxc : (d == 1) ? byc : bzc;
                    const float vc = (d == 0) ? vx[it] : (d == 1) ? vy[it] : vz[it];
                    o[j4] = fmaf(DT, vc, bc);
                }
                __stwt(q + gg, make_float4(o[0], o[1], o[2], o[3]));
            }
        } else {
            #pragma unroll
            for (int j = 0; j < ITEMS; j++) {
                if (t0 + j < T) {
                    float* o = xrow + (size_t)(t0 + j) * 3;
                    o[0] = fmaf(DT, vx[j], bxc);
                    o[1] = fmaf(DT, vy[j], byc);
                    o[2] = fmaf(DT, vz[j], bzc);
                }
            }
        }

        pk_cur = pk_next;
    }
    #undef ISSUE_FOR_CHUNK
}

extern "C" void kernel_launch(void* const* d_in, const int* in_sizes, int n_in,
                              void* d_out, int out_size)
{
    const int*   states = (const int*)  d_in[0];
    const float* e0s    = (const float*)d_in[1];
    const float* sp0    = (const float*)d_in[2];
    const float* sp1    = (const float*)d_in[3];
    const float* x0     = (const float*)d_in[4];
    float*       X      = (float*)d_out;

    const int B = in_sizes[2];           // speed_0 has B elements
    const int T = in_sizes[0] / B;       // states is (B, T)
    const int P = (T + CHUNK - 1) / CHUNK;

    const size_t smem = (size_t)P * THREADS * sizeof(uint16_t)
                      + (size_t)P * NWARPS * sizeof(int);
    traj_scan_kernel<<<B, THREADS, smem>>>(states, e0s, sp0, sp1, x0, X, T, P);
}